// round 16
// baseline (speedup 1.0000x reference)
#include <cuda_runtime.h>
#include <cuda_fp16.h>
#include <cstdint>
#include <cstring>

// Attention_75522704933073 — mma.sync pure-fp16 flash attention, v13.
// R15: counter reset folded into prep_kv (kills the 3.7us reset kernel +
//      launch gap); next work-item id fetched at the FIRST tile of the
//      current item (ATOMG latency hidden under compute; one less
//      __syncthreads per item). Hot loops identical to R14.
// Math: QK = Qfp16*Kfp16, PV = Pfp16*Vfp16, fp32 accum, fixed-max softmax in
// exp2 domain, sink in denominator only.

namespace {
constexpr int Bc = 4, Sc = 2048, Hc = 16, Dc = 128;
constexpr int BM = 128, BN = 64;
constexpr float kScale2 = 0.08838834764831845f * 1.4426950408889634f; // scale*log2e
constexpr int QSTR = Hc * Dc;
constexpr int KSTR = 4 * Dc;
constexpr int PITCH = 272;
constexpr int SM_Q = 0;            // 128 x 272 = 34816
constexpr int STG = 34816;
constexpr int STG_SZ = 34816;      // K(17408) + V(17408)
constexpr int OF_K = 0, OF_V = 17408;
constexpr int SM_W = STG + 2 * STG_SZ;         // 104448: work-id broadcast slot
constexpr int SMEM_BYTES = SM_W + 16;          // -> still 2 CTAs/SM
constexpr int TOK = Bc * Sc;
constexpr int N_ITEMS = 16 * Hc * Bc;          // 1024 work items
constexpr int N_PCTA = 296;                    // 148 SMs x 2
}

__device__ __align__(16) unsigned char g_k16[4 * TOK * 256];
__device__ __align__(16) unsigned char g_v16[4 * TOK * 256];
__device__ unsigned int g_ctr;

__device__ __forceinline__ uint32_t smem_u32(const void* p) {
    uint32_t a;
    asm("{ .reg .u64 t; cvta.to.shared.u64 t, %1; cvt.u32.u64 %0, t; }" : "=r"(a) : "l"(p));
    return a;
}
__device__ __forceinline__ void ldsm4(uint32_t addr, uint32_t r[4]) {
    asm volatile("ldmatrix.sync.aligned.m8n8.x4.shared.b16 {%0,%1,%2,%3}, [%4];"
                 : "=r"(r[0]), "=r"(r[1]), "=r"(r[2]), "=r"(r[3]) : "r"(addr));
}
__device__ __forceinline__ void ldsm4t(uint32_t addr, uint32_t r[4]) {
    asm volatile("ldmatrix.sync.aligned.m8n8.x4.trans.shared.b16 {%0,%1,%2,%3}, [%4];"
                 : "=r"(r[0]), "=r"(r[1]), "=r"(r[2]), "=r"(r[3]) : "r"(addr));
}
__device__ __forceinline__ void mma16816(float c[4], const uint32_t a[4],
                                         uint32_t b0, uint32_t b1) {
    asm("mma.sync.aligned.m16n8k16.row.col.f32.f16.f16.f32 "
        "{%0,%1,%2,%3}, {%4,%5,%6,%7}, {%8,%9}, {%0,%1,%2,%3};"
        : "+f"(c[0]), "+f"(c[1]), "+f"(c[2]), "+f"(c[3])
        : "r"(a[0]), "r"(a[1]), "r"(a[2]), "r"(a[3]), "r"(b0), "r"(b1));
}
__device__ __forceinline__ void cp16(uint32_t dst, const void* src) {
    asm volatile("cp.async.cg.shared.global [%0], [%1], 16;" :: "r"(dst), "l"(src) : "memory");
}
#define CP_COMMIT() asm volatile("cp.async.commit_group;" ::: "memory")
#define CP_WAIT0()  asm volatile("cp.async.wait_group 0;"  ::: "memory")

__device__ __forceinline__ uint32_t h2u(__half2 v) {
    uint32_t r; memcpy(&r, &v, 4); return r;
}
__device__ __forceinline__ float ex2(float x) {
    float y; asm("ex2.approx.f32 %0, %1;" : "=f"(y) : "f"(x)); return y;
}

// ---- prep: K,V fp32 -> fp16, regrouped [hk][token][dim]; also resets ctr ----
__global__ __launch_bounds__(256)
void prep_kv(const float* __restrict__ K, const float* __restrict__ V) {
    if (blockIdx.x == 0 && threadIdx.x == 0) g_ctr = 0u;   // visible to attn_mma
    const int s = blockIdx.x * 256 + threadIdx.x;
    const int hk = s >> 18;
    const int t  = (s >> 5) & (TOK - 1);
    const int c4 = s & 31;
    const size_t gsrc = (size_t)t * KSTR + hk * Dc + 4 * c4;
    const size_t gdst = ((size_t)hk * TOK + t) * 256 + c4 * 8;
    float4 x = *(const float4*)(K + gsrc);
    *(uint2*)(g_k16 + gdst) =
        make_uint2(h2u(__floats2half2_rn(x.x, x.y)), h2u(__floats2half2_rn(x.z, x.w)));
    x = *(const float4*)(V + gsrc);
    *(uint2*)(g_v16 + gdst) =
        make_uint2(h2u(__floats2half2_rn(x.x, x.y)), h2u(__floats2half2_rn(x.z, x.w)));
}

__device__ __forceinline__ void issue_tile(uint32_t sb, int stage, int tid,
                                           size_t base) {
    const uint32_t sd = sb + STG + stage * STG_SZ;
    #pragma unroll
    for (int it = 0; it < 8; ++it) {
        const int slot = it * 128 + tid;       // 64 rows x 16 chunks
        const int row = slot >> 4, c = slot & 15;
        const int sm = row * PITCH + c * 16;
        const int gm = row * 256 + c * 16;
        cp16(sd + OF_K + sm, g_k16 + base + gm);
        cp16(sd + OF_V + sm, g_v16 + base + gm);
    }
    CP_COMMIT();
}

__global__ __launch_bounds__(128, 2)
void attn_mma(const float* __restrict__ Q, const float* __restrict__ SNK,
              float* __restrict__ O)
{
    extern __shared__ char smem[];
    const uint32_t sb = smem_u32(smem);
    volatile unsigned int* wslot = (volatile unsigned int*)(smem + SM_W);
    const int tid = threadIdx.x, wid = tid >> 5, lane = tid & 31;
    const int g = lane >> 2, tig = lane & 3;
    const int wr = wid * 32;           // this warp's 32 query rows

    // fragment offsets (item-invariant)
    const uint32_t kfo = (uint32_t)(((lane & 7) + ((lane >> 4) & 1) * 8) * PITCH
                                    + ((lane >> 3) & 1) * 16);
    const uint32_t vfo = (uint32_t)(((lane & 7) + ((lane >> 3) & 1) * 8) * PITCH
                                    + ((lane >> 4) & 1) * 16);

    // first work item
    if (tid == 0) *wslot = atomicAdd(&g_ctr, 1u);
    __syncthreads();
    unsigned int w = *wslot;

    while (w < (unsigned)N_ITEMS) {
        // decode: qt descending (LPT), then b, then h (GQA heads adjacent)
        const int qt = 15 - (int)(w >> 6);
        const int r  = (int)(w & 63u);
        const int b  = r >> 4;
        const int h  = r & 15;
        const int hk = h >> 2;
        const int ibase = qt * BM;
        const int iw = ibase + wr;

        const int kt0 = max(0, 2 * qt - 16);
        const int kt1 = 2 * qt + 1;
        const size_t kvroot = ((size_t)hk * TOK + b * Sc) * 256;

        issue_tile(sb, 0, tid, kvroot + (size_t)kt0 * BN * 256);

        // ---- Q: fp32 -> (scale*log2e)-scaled fp16 -> smem ----
        #pragma unroll
        for (int it = 0; it < 32; ++it) {
            const int slot = it * 128 + tid;
            const int row = slot >> 5, c4 = slot & 31;
            float4 x = *(const float4*)(Q + (size_t)(b * Sc + ibase + row) * QSTR
                                        + h * Dc + 4 * c4);
            __half2 a = __floats2half2_rn(x.x * kScale2, x.y * kScale2);
            __half2 c = __floats2half2_rn(x.z * kScale2, x.w * kScale2);
            *(uint2*)(smem + SM_Q + row * PITCH + c4 * 8) = make_uint2(h2u(a), h2u(c));
        }
        __syncthreads();

        const uint32_t qfb0 = sb + SM_Q
            + (wr + (lane & 7) + ((lane >> 3) & 1) * 8) * PITCH
            + ((lane >> 4) & 1) * 16;
        const uint32_t qfb1 = qfb0 + 16 * PITCH;

        float oacc[2][16][4];
        #pragma unroll
        for (int mi = 0; mi < 2; ++mi)
            #pragma unroll
            for (int n = 0; n < 16; ++n)
                oacc[mi][n][0] = oacc[mi][n][1] = oacc[mi][n][2] = oacc[mi][n][3] = 0.f;
        float lsA[2] = {0.f, 0.f}, lsB[2] = {0.f, 0.f};

        for (int kt = kt0; kt <= kt1; ++kt) {
            const int kbase = kt * BN;
            const int stage = (kt - kt0) & 1;
            const uint32_t sd = sb + STG + stage * STG_SZ;

            CP_WAIT0();
            __syncthreads();
            if (kt < kt1)
                issue_tile(sb, stage ^ 1, tid, kvroot + (size_t)(kt + 1) * BN * 256);
            // overlap the next-item fetch with the first tile's compute;
            // consumed only after the post-epilogue __syncthreads.
            if (kt == kt0 && tid == 0) *wslot = atomicAdd(&g_ctr, 1u);

            const bool interior = (kbase + (BN - 1) <= iw) && (iw + 31 - kbase <= 1024);

            if (interior) {
                // ---- QK over full 64-key tile ----
                float c[2][8][4] = {};
                #pragma unroll
                for (int kk = 0; kk < 8; ++kk) {
                    uint32_t qf0[4], qf1[4];
                    ldsm4(qfb0 + kk * 32, qf0);
                    ldsm4(qfb1 + kk * 32, qf1);
                    #pragma unroll
                    for (int nb = 0; nb < 4; ++nb) {
                        uint32_t bk[4];
                        ldsm4(sd + OF_K + kfo + nb * (16 * PITCH) + kk * 32, bk);
                        mma16816(c[0][2 * nb],     qf0, bk[0], bk[1]);
                        mma16816(c[0][2 * nb + 1], qf0, bk[2], bk[3]);
                        mma16816(c[1][2 * nb],     qf1, bk[0], bk[1]);
                        mma16816(c[1][2 * nb + 1], qf1, bk[2], bk[3]);
                    }
                }
                // ---- softmax: p = 2^s ----
                uint32_t ph[2][4][4];
                #pragma unroll
                for (int mi = 0; mi < 2; ++mi) {
                    float a0 = 0.f, a1 = 0.f, b0 = 0.f, b1 = 0.f;
                    #pragma unroll
                    for (int nb = 0; nb < 8; ++nb) {
                        const float p00 = ex2(c[mi][nb][0]);
                        const float p01 = ex2(c[mi][nb][1]);
                        const float p10 = ex2(c[mi][nb][2]);
                        const float p11 = ex2(c[mi][nb][3]);
                        if (nb & 1) { a1 += p00 + p01; b1 += p10 + p11; }
                        else        { a0 += p00 + p01; b0 += p10 + p11; }
                        const int kj = nb >> 1, half = nb & 1;
                        ph[mi][kj][2 * half]     = h2u(__floats2half2_rn(p00, p01));
                        ph[mi][kj][2 * half + 1] = h2u(__floats2half2_rn(p10, p11));
                    }
                    lsA[mi] += a0 + a1;
                    lsB[mi] += b0 + b1;
                }
                // ---- PV over the whole tile ----
                #pragma unroll
                for (int kj = 0; kj < 4; ++kj) {
                    #pragma unroll
                    for (int nbv = 0; nbv < 8; ++nbv) {
                        uint32_t bv[4];
                        ldsm4t(sd + OF_V + vfo + kj * (16 * PITCH) + nbv * 32, bv);
                        mma16816(oacc[0][2 * nbv],     ph[0][kj], bv[0], bv[1]);
                        mma16816(oacc[0][2 * nbv + 1], ph[0][kj], bv[2], bv[3]);
                        mma16816(oacc[1][2 * nbv],     ph[1][kj], bv[0], bv[1]);
                        mma16816(oacc[1][2 * nbv + 1], ph[1][kj], bv[2], bv[3]);
                    }
                }
            } else {
                // ---- boundary: two 32-key halves, block vis + elem mask ----
                bool vis[4];
                #pragma unroll
                for (int nbg = 0; nbg < 4; ++nbg) {
                    const int jlo = kbase + 16 * nbg;
                    vis[nbg] = (jlo <= iw + 31) && (jlo + 15 >= iw - 1024);
                }
                #pragma unroll
                for (int hj = 0; hj < 2; ++hj) {
                    float c[2][4][4] = {};
                    #pragma unroll
                    for (int kk = 0; kk < 8; ++kk) {
                        uint32_t qf0[4], qf1[4];
                        ldsm4(qfb0 + kk * 32, qf0);
                        ldsm4(qfb1 + kk * 32, qf1);
                        #pragma unroll
                        for (int nbh = 0; nbh < 2; ++nbh) {
                            if (!vis[2 * hj + nbh]) continue;
                            uint32_t bk[4];
                            ldsm4(sd + OF_K + kfo + (2 * hj + nbh) * (16 * PITCH) + kk * 32, bk);
                            mma16816(c[0][2 * nbh],     qf0, bk[0], bk[1]);
                            mma16816(c[0][2 * nbh + 1], qf0, bk[2], bk[3]);
                            mma16816(c[1][2 * nbh],     qf1, bk[0], bk[1]);
                            mma16816(c[1][2 * nbh + 1], qf1, bk[2], bk[3]);
                        }
                    }
                    uint32_t ph[2][2][4];
                    #pragma unroll
                    for (int mi = 0; mi < 2; ++mi) {
                        const int i0 = iw + 16 * mi + g, i1 = i0 + 8;
                        #pragma unroll
                        for (int nb = 0; nb < 4; ++nb) {
                            const int j0 = kbase + 32 * hj + 8 * nb + 2 * tig;
                            const float p00 = ((unsigned)(i0 - j0)     <= 1024u) ? ex2(c[mi][nb][0]) : 0.f;
                            const float p01 = ((unsigned)(i0 - j0 - 1) <= 1024u) ? ex2(c[mi][nb][1]) : 0.f;
                            const float p10 = ((unsigned)(i1 - j0)     <= 1024u) ? ex2(c[mi][nb][2]) : 0.f;
                            const float p11 = ((unsigned)(i1 - j0 - 1) <= 1024u) ? ex2(c[mi][nb][3]) : 0.f;
                            lsA[mi] += p00 + p01; lsB[mi] += p10 + p11;
                            const int kj = nb >> 1, half = nb & 1;
                            ph[mi][kj][2 * half]     = h2u(__floats2half2_rn(p00, p01));
                            ph[mi][kj][2 * half + 1] = h2u(__floats2half2_rn(p10, p11));
                        }
                    }
                    #pragma unroll
                    for (int kj = 0; kj < 2; ++kj) {
                        if (!vis[2 * hj + kj]) continue;
                        #pragma unroll
                        for (int nbv = 0; nbv < 8; ++nbv) {
                            uint32_t bv[4];
                            ldsm4t(sd + OF_V + vfo + (2 * hj + kj) * (16 * PITCH) + nbv * 32, bv);
                            mma16816(oacc[0][2 * nbv],     ph[0][kj], bv[0], bv[1]);
                            mma16816(oacc[0][2 * nbv + 1], ph[0][kj], bv[2], bv[3]);
                            mma16816(oacc[1][2 * nbv],     ph[1][kj], bv[0], bv[1]);
                            mma16816(oacc[1][2 * nbv + 1], ph[1][kj], bv[2], bv[3]);
                        }
                    }
                }
            }
        }

        // ---- epilogue: quad-reduce row sums, add sink, normalize, store ----
        #pragma unroll
        for (int mi = 0; mi < 2; ++mi) {
            lsA[mi] += __shfl_xor_sync(0xffffffffu, lsA[mi], 1);
            lsA[mi] += __shfl_xor_sync(0xffffffffu, lsA[mi], 2);
            lsB[mi] += __shfl_xor_sync(0xffffffffu, lsB[mi], 1);
            lsB[mi] += __shfl_xor_sync(0xffffffffu, lsB[mi], 2);
        }
        const float es = __expf(SNK[h]);
        #pragma unroll
        for (int mi = 0; mi < 2; ++mi) {
            const float invA = 1.f / (lsA[mi] + es);
            const float invB = 1.f / (lsB[mi] + es);
            const int i0 = iw + 16 * mi + g;
            float* o0 = O + (size_t)(b * Sc + i0) * QSTR + h * Dc;
            float* o1 = o0 + (size_t)8 * QSTR;
            #pragma unroll
            for (int nb = 0; nb < 16; ++nb) {
                const int col = 8 * nb + 2 * tig;
                *(float2*)(o0 + col) =
                    make_float2(oacc[mi][nb][0] * invA, oacc[mi][nb][1] * invA);
                *(float2*)(o1 + col) =
                    make_float2(oacc[mi][nb][2] * invB, oacc[mi][nb][3] * invB);
            }
        }

        __syncthreads();               // wslot (next id) + smem reuse safe
        w = *wslot;
    }
}

extern "C" void kernel_launch(void* const* d_in, const int* in_sizes, int n_in,
                              void* d_out, int out_size) {
    (void)in_sizes; (void)n_in; (void)out_size;
    cudaFuncSetAttribute(attn_mma, cudaFuncAttributeMaxDynamicSharedMemorySize, SMEM_BYTES);
    const float* q   = (const float*)d_in[0];
    const float* k   = (const float*)d_in[1];
    const float* v   = (const float*)d_in[2];
    const float* snk = (const float*)d_in[3];
    prep_kv<<<4096, 256>>>(k, v);
    attn_mma<<<N_PCTA, 128, SMEM_BYTES>>>(q, snk, (float*)d_out);
}

// round 17
// speedup vs baseline: 1.0490x; 1.0490x over previous
#include <cuda_runtime.h>
#include <cuda_fp16.h>
#include <cstdint>
#include <cstring>

// Attention_75522704933073 — mma.sync pure-fp16 flash attention, v14.
// R16: revert R15's work-item PREFETCH (it pre-assigned items one step early
//      and broke LPT dynamic balancing -> +8us). Keep the counter reset folded
//      into prep_kv (saves the reset kernel + launch gap). Work stealing is
//      just-in-time again: fetch at item end, exactly as in R14.
// Math: QK = Qfp16*Kfp16, PV = Pfp16*Vfp16, fp32 accum, fixed-max softmax in
// exp2 domain, sink in denominator only.

namespace {
constexpr int Bc = 4, Sc = 2048, Hc = 16, Dc = 128;
constexpr int BM = 128, BN = 64;
constexpr float kScale2 = 0.08838834764831845f * 1.4426950408889634f; // scale*log2e
constexpr int QSTR = Hc * Dc;
constexpr int KSTR = 4 * Dc;
constexpr int PITCH = 272;
constexpr int SM_Q = 0;            // 128 x 272 = 34816
constexpr int STG = 34816;
constexpr int STG_SZ = 34816;      // K(17408) + V(17408)
constexpr int OF_K = 0, OF_V = 17408;
constexpr int SM_W = STG + 2 * STG_SZ;         // 104448: work-id broadcast slot
constexpr int SMEM_BYTES = SM_W + 16;          // -> still 2 CTAs/SM
constexpr int TOK = Bc * Sc;
constexpr int N_ITEMS = 16 * Hc * Bc;          // 1024 work items
constexpr int N_PCTA = 296;                    // 148 SMs x 2
}

__device__ __align__(16) unsigned char g_k16[4 * TOK * 256];
__device__ __align__(16) unsigned char g_v16[4 * TOK * 256];
__device__ unsigned int g_ctr;

__device__ __forceinline__ uint32_t smem_u32(const void* p) {
    uint32_t a;
    asm("{ .reg .u64 t; cvta.to.shared.u64 t, %1; cvt.u32.u64 %0, t; }" : "=r"(a) : "l"(p));
    return a;
}
__device__ __forceinline__ void ldsm4(uint32_t addr, uint32_t r[4]) {
    asm volatile("ldmatrix.sync.aligned.m8n8.x4.shared.b16 {%0,%1,%2,%3}, [%4];"
                 : "=r"(r[0]), "=r"(r[1]), "=r"(r[2]), "=r"(r[3]) : "r"(addr));
}
__device__ __forceinline__ void ldsm4t(uint32_t addr, uint32_t r[4]) {
    asm volatile("ldmatrix.sync.aligned.m8n8.x4.trans.shared.b16 {%0,%1,%2,%3}, [%4];"
                 : "=r"(r[0]), "=r"(r[1]), "=r"(r[2]), "=r"(r[3]) : "r"(addr));
}
__device__ __forceinline__ void mma16816(float c[4], const uint32_t a[4],
                                         uint32_t b0, uint32_t b1) {
    asm("mma.sync.aligned.m16n8k16.row.col.f32.f16.f16.f32 "
        "{%0,%1,%2,%3}, {%4,%5,%6,%7}, {%8,%9}, {%0,%1,%2,%3};"
        : "+f"(c[0]), "+f"(c[1]), "+f"(c[2]), "+f"(c[3])
        : "r"(a[0]), "r"(a[1]), "r"(a[2]), "r"(a[3]), "r"(b0), "r"(b1));
}
__device__ __forceinline__ void cp16(uint32_t dst, const void* src) {
    asm volatile("cp.async.cg.shared.global [%0], [%1], 16;" :: "r"(dst), "l"(src) : "memory");
}
#define CP_COMMIT() asm volatile("cp.async.commit_group;" ::: "memory")
#define CP_WAIT0()  asm volatile("cp.async.wait_group 0;"  ::: "memory")

__device__ __forceinline__ uint32_t h2u(__half2 v) {
    uint32_t r; memcpy(&r, &v, 4); return r;
}
__device__ __forceinline__ float ex2(float x) {
    float y; asm("ex2.approx.f32 %0, %1;" : "=f"(y) : "f"(x)); return y;
}

// ---- prep: K,V fp32 -> fp16, regrouped [hk][token][dim]; also resets ctr ----
__global__ __launch_bounds__(256)
void prep_kv(const float* __restrict__ K, const float* __restrict__ V) {
    if (blockIdx.x == 0 && threadIdx.x == 0) g_ctr = 0u;   // stream-ordered vs attn_mma
    const int s = blockIdx.x * 256 + threadIdx.x;
    const int hk = s >> 18;
    const int t  = (s >> 5) & (TOK - 1);
    const int c4 = s & 31;
    const size_t gsrc = (size_t)t * KSTR + hk * Dc + 4 * c4;
    const size_t gdst = ((size_t)hk * TOK + t) * 256 + c4 * 8;
    float4 x = *(const float4*)(K + gsrc);
    *(uint2*)(g_k16 + gdst) =
        make_uint2(h2u(__floats2half2_rn(x.x, x.y)), h2u(__floats2half2_rn(x.z, x.w)));
    x = *(const float4*)(V + gsrc);
    *(uint2*)(g_v16 + gdst) =
        make_uint2(h2u(__floats2half2_rn(x.x, x.y)), h2u(__floats2half2_rn(x.z, x.w)));
}

__device__ __forceinline__ void issue_tile(uint32_t sb, int stage, int tid,
                                           size_t base) {
    const uint32_t sd = sb + STG + stage * STG_SZ;
    #pragma unroll
    for (int it = 0; it < 8; ++it) {
        const int slot = it * 128 + tid;       // 64 rows x 16 chunks
        const int row = slot >> 4, c = slot & 15;
        const int sm = row * PITCH + c * 16;
        const int gm = row * 256 + c * 16;
        cp16(sd + OF_K + sm, g_k16 + base + gm);
        cp16(sd + OF_V + sm, g_v16 + base + gm);
    }
    CP_COMMIT();
}

__global__ __launch_bounds__(128, 2)
void attn_mma(const float* __restrict__ Q, const float* __restrict__ SNK,
              float* __restrict__ O)
{
    extern __shared__ char smem[];
    const uint32_t sb = smem_u32(smem);
    volatile unsigned int* wslot = (volatile unsigned int*)(smem + SM_W);
    const int tid = threadIdx.x, wid = tid >> 5, lane = tid & 31;
    const int g = lane >> 2, tig = lane & 3;
    const int wr = wid * 32;           // this warp's 32 query rows

    // fragment offsets (item-invariant)
    const uint32_t kfo = (uint32_t)(((lane & 7) + ((lane >> 4) & 1) * 8) * PITCH
                                    + ((lane >> 3) & 1) * 16);
    const uint32_t vfo = (uint32_t)(((lane & 7) + ((lane >> 3) & 1) * 8) * PITCH
                                    + ((lane >> 4) & 1) * 16);

    for (;;) {
        __syncthreads();               // smem from previous item fully consumed
        if (tid == 0) *wslot = atomicAdd(&g_ctr, 1u);   // just-in-time steal
        __syncthreads();
        const unsigned int w = *wslot;
        if (w >= (unsigned)N_ITEMS) break;

        // decode: qt descending (LPT), then b, then h (GQA heads adjacent)
        const int qt = 15 - (int)(w >> 6);
        const int r  = (int)(w & 63u);
        const int b  = r >> 4;
        const int h  = r & 15;
        const int hk = h >> 2;
        const int ibase = qt * BM;
        const int iw = ibase + wr;

        const int kt0 = max(0, 2 * qt - 16);
        const int kt1 = 2 * qt + 1;
        const size_t kvroot = ((size_t)hk * TOK + b * Sc) * 256;

        issue_tile(sb, 0, tid, kvroot + (size_t)kt0 * BN * 256);

        // ---- Q: fp32 -> (scale*log2e)-scaled fp16 -> smem ----
        #pragma unroll
        for (int it = 0; it < 32; ++it) {
            const int slot = it * 128 + tid;
            const int row = slot >> 5, c4 = slot & 31;
            float4 x = *(const float4*)(Q + (size_t)(b * Sc + ibase + row) * QSTR
                                        + h * Dc + 4 * c4);
            __half2 a = __floats2half2_rn(x.x * kScale2, x.y * kScale2);
            __half2 c = __floats2half2_rn(x.z * kScale2, x.w * kScale2);
            *(uint2*)(smem + SM_Q + row * PITCH + c4 * 8) = make_uint2(h2u(a), h2u(c));
        }
        __syncthreads();

        const uint32_t qfb0 = sb + SM_Q
            + (wr + (lane & 7) + ((lane >> 3) & 1) * 8) * PITCH
            + ((lane >> 4) & 1) * 16;
        const uint32_t qfb1 = qfb0 + 16 * PITCH;

        float oacc[2][16][4];
        #pragma unroll
        for (int mi = 0; mi < 2; ++mi)
            #pragma unroll
            for (int n = 0; n < 16; ++n)
                oacc[mi][n][0] = oacc[mi][n][1] = oacc[mi][n][2] = oacc[mi][n][3] = 0.f;
        float lsA[2] = {0.f, 0.f}, lsB[2] = {0.f, 0.f};

        for (int kt = kt0; kt <= kt1; ++kt) {
            const int kbase = kt * BN;
            const int stage = (kt - kt0) & 1;
            const uint32_t sd = sb + STG + stage * STG_SZ;

            CP_WAIT0();
            __syncthreads();
            if (kt < kt1)
                issue_tile(sb, stage ^ 1, tid, kvroot + (size_t)(kt + 1) * BN * 256);

            const bool interior = (kbase + (BN - 1) <= iw) && (iw + 31 - kbase <= 1024);

            if (interior) {
                // ---- QK over full 64-key tile ----
                float c[2][8][4] = {};
                #pragma unroll
                for (int kk = 0; kk < 8; ++kk) {
                    uint32_t qf0[4], qf1[4];
                    ldsm4(qfb0 + kk * 32, qf0);
                    ldsm4(qfb1 + kk * 32, qf1);
                    #pragma unroll
                    for (int nb = 0; nb < 4; ++nb) {
                        uint32_t bk[4];
                        ldsm4(sd + OF_K + kfo + nb * (16 * PITCH) + kk * 32, bk);
                        mma16816(c[0][2 * nb],     qf0, bk[0], bk[1]);
                        mma16816(c[0][2 * nb + 1], qf0, bk[2], bk[3]);
                        mma16816(c[1][2 * nb],     qf1, bk[0], bk[1]);
                        mma16816(c[1][2 * nb + 1], qf1, bk[2], bk[3]);
                    }
                }
                // ---- softmax: p = 2^s ----
                uint32_t ph[2][4][4];
                #pragma unroll
                for (int mi = 0; mi < 2; ++mi) {
                    float a0 = 0.f, a1 = 0.f, b0 = 0.f, b1 = 0.f;
                    #pragma unroll
                    for (int nb = 0; nb < 8; ++nb) {
                        const float p00 = ex2(c[mi][nb][0]);
                        const float p01 = ex2(c[mi][nb][1]);
                        const float p10 = ex2(c[mi][nb][2]);
                        const float p11 = ex2(c[mi][nb][3]);
                        if (nb & 1) { a1 += p00 + p01; b1 += p10 + p11; }
                        else        { a0 += p00 + p01; b0 += p10 + p11; }
                        const int kj = nb >> 1, half = nb & 1;
                        ph[mi][kj][2 * half]     = h2u(__floats2half2_rn(p00, p01));
                        ph[mi][kj][2 * half + 1] = h2u(__floats2half2_rn(p10, p11));
                    }
                    lsA[mi] += a0 + a1;
                    lsB[mi] += b0 + b1;
                }
                // ---- PV over the whole tile ----
                #pragma unroll
                for (int kj = 0; kj < 4; ++kj) {
                    #pragma unroll
                    for (int nbv = 0; nbv < 8; ++nbv) {
                        uint32_t bv[4];
                        ldsm4t(sd + OF_V + vfo + kj * (16 * PITCH) + nbv * 32, bv);
                        mma16816(oacc[0][2 * nbv],     ph[0][kj], bv[0], bv[1]);
                        mma16816(oacc[0][2 * nbv + 1], ph[0][kj], bv[2], bv[3]);
                        mma16816(oacc[1][2 * nbv],     ph[1][kj], bv[0], bv[1]);
                        mma16816(oacc[1][2 * nbv + 1], ph[1][kj], bv[2], bv[3]);
                    }
                }
            } else {
                // ---- boundary: two 32-key halves, block vis + elem mask ----
                bool vis[4];
                #pragma unroll
                for (int nbg = 0; nbg < 4; ++nbg) {
                    const int jlo = kbase + 16 * nbg;
                    vis[nbg] = (jlo <= iw + 31) && (jlo + 15 >= iw - 1024);
                }
                #pragma unroll
                for (int hj = 0; hj < 2; ++hj) {
                    float c[2][4][4] = {};
                    #pragma unroll
                    for (int kk = 0; kk < 8; ++kk) {
                        uint32_t qf0[4], qf1[4];
                        ldsm4(qfb0 + kk * 32, qf0);
                        ldsm4(qfb1 + kk * 32, qf1);
                        #pragma unroll
                        for (int nbh = 0; nbh < 2; ++nbh) {
                            if (!vis[2 * hj + nbh]) continue;
                            uint32_t bk[4];
                            ldsm4(sd + OF_K + kfo + (2 * hj + nbh) * (16 * PITCH) + kk * 32, bk);
                            mma16816(c[0][2 * nbh],     qf0, bk[0], bk[1]);
                            mma16816(c[0][2 * nbh + 1], qf0, bk[2], bk[3]);
                            mma16816(c[1][2 * nbh],     qf1, bk[0], bk[1]);
                            mma16816(c[1][2 * nbh + 1], qf1, bk[2], bk[3]);
                        }
                    }
                    uint32_t ph[2][2][4];
                    #pragma unroll
                    for (int mi = 0; mi < 2; ++mi) {
                        const int i0 = iw + 16 * mi + g, i1 = i0 + 8;
                        #pragma unroll
                        for (int nb = 0; nb < 4; ++nb) {
                            const int j0 = kbase + 32 * hj + 8 * nb + 2 * tig;
                            const float p00 = ((unsigned)(i0 - j0)     <= 1024u) ? ex2(c[mi][nb][0]) : 0.f;
                            const float p01 = ((unsigned)(i0 - j0 - 1) <= 1024u) ? ex2(c[mi][nb][1]) : 0.f;
                            const float p10 = ((unsigned)(i1 - j0)     <= 1024u) ? ex2(c[mi][nb][2]) : 0.f;
                            const float p11 = ((unsigned)(i1 - j0 - 1) <= 1024u) ? ex2(c[mi][nb][3]) : 0.f;
                            lsA[mi] += p00 + p01; lsB[mi] += p10 + p11;
                            const int kj = nb >> 1, half = nb & 1;
                            ph[mi][kj][2 * half]     = h2u(__floats2half2_rn(p00, p01));
                            ph[mi][kj][2 * half + 1] = h2u(__floats2half2_rn(p10, p11));
                        }
                    }
                    #pragma unroll
                    for (int kj = 0; kj < 2; ++kj) {
                        if (!vis[2 * hj + kj]) continue;
                        #pragma unroll
                        for (int nbv = 0; nbv < 8; ++nbv) {
                            uint32_t bv[4];
                            ldsm4t(sd + OF_V + vfo + (2 * hj + kj) * (16 * PITCH) + nbv * 32, bv);
                            mma16816(oacc[0][2 * nbv],     ph[0][kj], bv[0], bv[1]);
                            mma16816(oacc[0][2 * nbv + 1], ph[0][kj], bv[2], bv[3]);
                            mma16816(oacc[1][2 * nbv],     ph[1][kj], bv[0], bv[1]);
                            mma16816(oacc[1][2 * nbv + 1], ph[1][kj], bv[2], bv[3]);
                        }
                    }
                }
            }
        }

        // ---- epilogue: quad-reduce row sums, add sink, normalize, store ----
        #pragma unroll
        for (int mi = 0; mi < 2; ++mi) {
            lsA[mi] += __shfl_xor_sync(0xffffffffu, lsA[mi], 1);
            lsA[mi] += __shfl_xor_sync(0xffffffffu, lsA[mi], 2);
            lsB[mi] += __shfl_xor_sync(0xffffffffu, lsB[mi], 1);
            lsB[mi] += __shfl_xor_sync(0xffffffffu, lsB[mi], 2);
        }
        const float es = __expf(SNK[h]);
        #pragma unroll
        for (int mi = 0; mi < 2; ++mi) {
            const float invA = 1.f / (lsA[mi] + es);
            const float invB = 1.f / (lsB[mi] + es);
            const int i0 = iw + 16 * mi + g;
            float* o0 = O + (size_t)(b * Sc + i0) * QSTR + h * Dc;
            float* o1 = o0 + (size_t)8 * QSTR;
            #pragma unroll
            for (int nb = 0; nb < 16; ++nb) {
                const int col = 8 * nb + 2 * tig;
                *(float2*)(o0 + col) =
                    make_float2(oacc[mi][nb][0] * invA, oacc[mi][nb][1] * invA);
                *(float2*)(o1 + col) =
                    make_float2(oacc[mi][nb][2] * invB, oacc[mi][nb][3] * invB);
            }
        }
    }
}

extern "C" void kernel_launch(void* const* d_in, const int* in_sizes, int n_in,
                              void* d_out, int out_size) {
    (void)in_sizes; (void)n_in; (void)out_size;
    cudaFuncSetAttribute(attn_mma, cudaFuncAttributeMaxDynamicSharedMemorySize, SMEM_BYTES);
    const float* q   = (const float*)d_in[0];
    const float* k   = (const float*)d_in[1];
    const float* v   = (const float*)d_in[2];
    const float* snk = (const float*)d_in[3];
    prep_kv<<<4096, 256>>>(k, v);
    attn_mma<<<N_PCTA, 128, SMEM_BYTES>>>(q, snk, (float*)d_out);
}